// round 4
// baseline (speedup 1.0000x reference)
#include <cuda_runtime.h>
#include <cuda_bf16.h>

#define N_NODES 100000
#define N_EDGES 1600000
#define D_IN    128
#define D_OUT   64

// Scratch for h = x @ W  (25.6 MB; __device__ global per allocation rules)
__device__ float g_h[(size_t)N_NODES * D_OUT];

// ---------------------------------------------------------------------------
// Kernel 1: zero the output (d_out is poisoned to 0xAA)
// ---------------------------------------------------------------------------
__global__ void zero_out_kernel(float4* __restrict__ out, int n4) {
    int i = blockIdx.x * blockDim.x + threadIdx.x;
    if (i < n4) out[i] = make_float4(0.f, 0.f, 0.f, 0.f);
}

// ---------------------------------------------------------------------------
// Kernel 2: h = x @ W
// Block: 256 threads = (4 col-groups) x (64 row-groups). Each thread computes
// a 4-row x 16-col register tile. W lives in smem (32 KB), broadcast reads.
// ---------------------------------------------------------------------------
__global__ __launch_bounds__(256, 2)
void gemm_kernel(const float* __restrict__ x, const float* __restrict__ W) {
    __shared__ float4 sW[D_IN][D_OUT / 4];   // [128][16] float4 = 32 KB

    int tid = threadIdx.x;
    // cooperative load of W (2048 float4)
    const float4* W4 = (const float4*)W;
    #pragma unroll
    for (int i = tid; i < D_IN * D_OUT / 4; i += 256)
        ((float4*)sW)[i] = W4[i];
    __syncthreads();

    int tx = tid & 3;          // col group: cols [tx*16, tx*16+16)
    int ty = tid >> 2;         // row group: 4 rows each
    int m0 = blockIdx.x * 256 + ty * 4;
    int j0 = tx * 4;           // float4 column index base (16 floats)

    float4 acc[4][4];
    #pragma unroll
    for (int r = 0; r < 4; r++)
        #pragma unroll
        for (int q = 0; q < 4; q++)
            acc[r][q] = make_float4(0.f, 0.f, 0.f, 0.f);

    const float4* x4 = (const float4*)x;

    for (int k4 = 0; k4 < D_IN / 4; k4++) {
        float xs[4][4];
        #pragma unroll
        for (int r = 0; r < 4; r++) {
            int m = m0 + r;
            float4 v = (m < N_NODES) ? x4[(size_t)m * (D_IN / 4) + k4]
                                     : make_float4(0.f, 0.f, 0.f, 0.f);
            xs[r][0] = v.x; xs[r][1] = v.y; xs[r][2] = v.z; xs[r][3] = v.w;
        }
        #pragma unroll
        for (int kk = 0; kk < 4; kk++) {
            int k = k4 * 4 + kk;
            float4 w0 = sW[k][j0 + 0];
            float4 w1 = sW[k][j0 + 1];
            float4 w2 = sW[k][j0 + 2];
            float4 w3 = sW[k][j0 + 3];
            #pragma unroll
            for (int r = 0; r < 4; r++) {
                float a = xs[r][kk];
                acc[r][0].x += a * w0.x; acc[r][0].y += a * w0.y;
                acc[r][0].z += a * w0.z; acc[r][0].w += a * w0.w;
                acc[r][1].x += a * w1.x; acc[r][1].y += a * w1.y;
                acc[r][1].z += a * w1.z; acc[r][1].w += a * w1.w;
                acc[r][2].x += a * w2.x; acc[r][2].y += a * w2.y;
                acc[r][2].z += a * w2.z; acc[r][2].w += a * w2.w;
                acc[r][3].x += a * w3.x; acc[r][3].y += a * w3.y;
                acc[r][3].z += a * w3.z; acc[r][3].w += a * w3.w;
            }
        }
    }

    #pragma unroll
    for (int r = 0; r < 4; r++) {
        int m = m0 + r;
        if (m < N_NODES) {
            float4* hp = (float4*)(g_h + (size_t)m * D_OUT) + j0;
            hp[0] = acc[r][0];
            hp[1] = acc[r][1];
            hp[2] = acc[r][2];
            hp[3] = acc[r][3];
        }
    }
}

// ---------------------------------------------------------------------------
// Kernel 3: scatter-add. 16 threads per edge, each handles 4 floats via
// vectorized L2 reduction (red.global.add.v4.f32, sm_90+).
// h fits in L2 (25.6 MB) so gathers are L2 hits.
// ---------------------------------------------------------------------------
__global__ __launch_bounds__(256)
void scatter_kernel(const int* __restrict__ edge_index, float* __restrict__ out) {
    int gid = blockIdx.x * blockDim.x + threadIdx.x;
    int e = gid >> 4;
    if (e >= N_EDGES) return;
    int c = (gid & 15) << 2;   // column offset 0,4,...,60

    int src = __ldg(edge_index + e);
    int dst = __ldg(edge_index + N_EDGES + e);

    float4 v = *(const float4*)(g_h + (size_t)src * D_OUT + c);
    float* p = out + (size_t)dst * D_OUT + c;
    asm volatile("red.global.add.v4.f32 [%0], {%1,%2,%3,%4};"
                 :: "l"(p), "f"(v.x), "f"(v.y), "f"(v.z), "f"(v.w)
                 : "memory");
}

// ---------------------------------------------------------------------------
// Kernel 4: out = relu(out + b)
// ---------------------------------------------------------------------------
__global__ void finish_kernel(float4* __restrict__ out,
                              const float* __restrict__ b, int n4) {
    int i = blockIdx.x * blockDim.x + threadIdx.x;
    if (i >= n4) return;
    int c = (i & (D_OUT / 4 - 1)) << 2;   // column base within row
    float4 v = out[i];
    v.x = fmaxf(v.x + __ldg(b + c + 0), 0.f);
    v.y = fmaxf(v.y + __ldg(b + c + 1), 0.f);
    v.z = fmaxf(v.z + __ldg(b + c + 2), 0.f);
    v.w = fmaxf(v.w + __ldg(b + c + 3), 0.f);
    out[i] = v;
}

// ---------------------------------------------------------------------------
extern "C" void kernel_launch(void* const* d_in, const int* in_sizes, int n_in,
                              void* d_out, int out_size) {
    const float* x          = (const float*)d_in[0];   // [100000, 128]
    const int*   edge_index = (const int*)d_in[1];     // [2, 1600000]
    const float* W          = (const float*)d_in[2];   // [128, 64]
    const float* b          = (const float*)d_in[3];   // [64]
    float*       out        = (float*)d_out;           // [100000, 64]

    int n4 = (N_NODES * D_OUT) / 4;   // 1.6M float4

    // 1) zero output
    zero_out_kernel<<<(n4 + 255) / 256, 256>>>((float4*)out, n4);

    // 2) h = x @ W
    gemm_kernel<<<(N_NODES + 255) / 256, 256>>>(x, W);

    // 3) scatter-add over edges (16 threads/edge)
    long long sthreads = (long long)N_EDGES * 16;
    scatter_kernel<<<(int)((sthreads + 255) / 256), 256>>>(edge_index, out);

    // 4) bias + relu
    finish_kernel<<<(n4 + 255) / 256, 256>>>((float4*)out, b, n4);
}

// round 5
// speedup vs baseline: 1.0020x; 1.0020x over previous
#include <cuda_runtime.h>
#include <cuda_bf16.h>

#define N_NODES 100000
#define N_EDGES 1600000
#define D_IN    128
#define D_OUT   64

// Scratch for h = x @ W  (25.6 MB; __device__ global per allocation rules)
__device__ float g_h[(size_t)N_NODES * D_OUT];

// ---------------------------------------------------------------------------
// Kernel 1: zero the output (d_out is poisoned to 0xAA)
// ---------------------------------------------------------------------------
__global__ void zero_out_kernel(float4* __restrict__ out, int n4) {
    int i = blockIdx.x * blockDim.x + threadIdx.x;
    if (i < n4) out[i] = make_float4(0.f, 0.f, 0.f, 0.f);
}

// ---------------------------------------------------------------------------
// Kernel 2: h = x @ W
// Block: 256 threads = (4 col-groups) x (64 row-groups). Each thread computes
// a 4-row x 16-col register tile. W lives in smem (32 KB), broadcast reads.
// ---------------------------------------------------------------------------
__global__ __launch_bounds__(256, 2)
void gemm_kernel(const float* __restrict__ x, const float* __restrict__ W) {
    __shared__ float4 sW[D_IN][D_OUT / 4];   // [128][16] float4 = 32 KB

    int tid = threadIdx.x;
    // cooperative load of W (2048 float4)
    const float4* W4 = (const float4*)W;
    #pragma unroll
    for (int i = tid; i < D_IN * D_OUT / 4; i += 256)
        ((float4*)sW)[i] = W4[i];
    __syncthreads();

    int tx = tid & 3;          // col group: cols [tx*16, tx*16+16)
    int ty = tid >> 2;         // row group: 4 rows each
    int m0 = blockIdx.x * 256 + ty * 4;
    int j0 = tx * 4;           // float4 column index base (16 floats)

    float4 acc[4][4];
    #pragma unroll
    for (int r = 0; r < 4; r++)
        #pragma unroll
        for (int q = 0; q < 4; q++)
            acc[r][q] = make_float4(0.f, 0.f, 0.f, 0.f);

    const float4* x4 = (const float4*)x;

    for (int k4 = 0; k4 < D_IN / 4; k4++) {
        float xs[4][4];
        #pragma unroll
        for (int r = 0; r < 4; r++) {
            int m = m0 + r;
            float4 v = (m < N_NODES) ? x4[(size_t)m * (D_IN / 4) + k4]
                                     : make_float4(0.f, 0.f, 0.f, 0.f);
            xs[r][0] = v.x; xs[r][1] = v.y; xs[r][2] = v.z; xs[r][3] = v.w;
        }
        #pragma unroll
        for (int kk = 0; kk < 4; kk++) {
            int k = k4 * 4 + kk;
            float4 w0 = sW[k][j0 + 0];
            float4 w1 = sW[k][j0 + 1];
            float4 w2 = sW[k][j0 + 2];
            float4 w3 = sW[k][j0 + 3];
            #pragma unroll
            for (int r = 0; r < 4; r++) {
                float a = xs[r][kk];
                acc[r][0].x += a * w0.x; acc[r][0].y += a * w0.y;
                acc[r][0].z += a * w0.z; acc[r][0].w += a * w0.w;
                acc[r][1].x += a * w1.x; acc[r][1].y += a * w1.y;
                acc[r][1].z += a * w1.z; acc[r][1].w += a * w1.w;
                acc[r][2].x += a * w2.x; acc[r][2].y += a * w2.y;
                acc[r][2].z += a * w2.z; acc[r][2].w += a * w2.w;
                acc[r][3].x += a * w3.x; acc[r][3].y += a * w3.y;
                acc[r][3].z += a * w3.z; acc[r][3].w += a * w3.w;
            }
        }
    }

    #pragma unroll
    for (int r = 0; r < 4; r++) {
        int m = m0 + r;
        if (m < N_NODES) {
            float4* hp = (float4*)(g_h + (size_t)m * D_OUT) + j0;
            hp[0] = acc[r][0];
            hp[1] = acc[r][1];
            hp[2] = acc[r][2];
            hp[3] = acc[r][3];
        }
    }
}

// ---------------------------------------------------------------------------
// Kernel 3: scatter-add. 16 threads per edge, each handles 4 floats via
// vectorized L2 reduction (red.global.add.v4.f32, sm_90+).
// h fits in L2 (25.6 MB) so gathers are L2 hits.
// ---------------------------------------------------------------------------
__global__ __launch_bounds__(256)
void scatter_kernel(const int* __restrict__ edge_index, float* __restrict__ out) {
    int gid = blockIdx.x * blockDim.x + threadIdx.x;
    int e = gid >> 4;
    if (e >= N_EDGES) return;
    int c = (gid & 15) << 2;   // column offset 0,4,...,60

    int src = __ldg(edge_index + e);
    int dst = __ldg(edge_index + N_EDGES + e);

    float4 v = *(const float4*)(g_h + (size_t)src * D_OUT + c);
    float* p = out + (size_t)dst * D_OUT + c;
    asm volatile("red.global.add.v4.f32 [%0], {%1,%2,%3,%4};"
                 :: "l"(p), "f"(v.x), "f"(v.y), "f"(v.z), "f"(v.w)
                 : "memory");
}

// ---------------------------------------------------------------------------
// Kernel 4: out = relu(out + b)
// ---------------------------------------------------------------------------
__global__ void finish_kernel(float4* __restrict__ out,
                              const float* __restrict__ b, int n4) {
    int i = blockIdx.x * blockDim.x + threadIdx.x;
    if (i >= n4) return;
    int c = (i & (D_OUT / 4 - 1)) << 2;   // column base within row
    float4 v = out[i];
    v.x = fmaxf(v.x + __ldg(b + c + 0), 0.f);
    v.y = fmaxf(v.y + __ldg(b + c + 1), 0.f);
    v.z = fmaxf(v.z + __ldg(b + c + 2), 0.f);
    v.w = fmaxf(v.w + __ldg(b + c + 3), 0.f);
    out[i] = v;
}

// ---------------------------------------------------------------------------
extern "C" void kernel_launch(void* const* d_in, const int* in_sizes, int n_in,
                              void* d_out, int out_size) {
    const float* x          = (const float*)d_in[0];   // [100000, 128]
    const int*   edge_index = (const int*)d_in[1];     // [2, 1600000]
    const float* W          = (const float*)d_in[2];   // [128, 64]
    const float* b          = (const float*)d_in[3];   // [64]
    float*       out        = (float*)d_out;           // [100000, 64]

    int n4 = (N_NODES * D_OUT) / 4;   // 1.6M float4

    // 1) zero output
    zero_out_kernel<<<(n4 + 255) / 256, 256>>>((float4*)out, n4);

    // 2) h = x @ W
    gemm_kernel<<<(N_NODES + 255) / 256, 256>>>(x, W);

    // 3) scatter-add over edges (16 threads/edge)
    long long sthreads = (long long)N_EDGES * 16;
    scatter_kernel<<<(int)((sthreads + 255) / 256), 256>>>(edge_index, out);

    // 4) bias + relu
    finish_kernel<<<(n4 + 255) / 256, 256>>>((float4*)out, b, n4);
}